// round 13
// baseline (speedup 1.0000x reference)
#include <cuda_runtime.h>
#include <cstdint>

// Problem constants (fixed by the reference)
#define Vn 100000
#define Tn 2
#define Nn 32
#define Fn 64
#define Mn 1600000
#define CAP 32   // bucket capacity; overflow -> list + fixup kernel (any input)

// Device scratch (zero-initialized at module load; restored every launch)
__device__ int   g_cnt[Tn * Vn];             // 800 KB  (reset by k4)
__device__ int   g_ridx[Tn][Vn * CAP];       // 25.6 MB
__device__ int   g_ovf_cnt[Tn];              // touched only by builds + k4 block 0
__device__ int   g_ovf[Tn][Mn];              // 12.8 MB (full-correctness bound)

#define ROWS_PER_THR 4
#define BUILD_BLOCKS ((Mn + 256 * ROWS_PER_THR - 1) / (256 * ROWS_PER_THR))  // 1563
#define GATHER_BLOCKS (Vn / 8)                                               // 12500
#define FIX_BLOCKS   128

// ---------------------------------------------------------------------------
// Build one t: 4 rows/thread. Atomics batched first (4 independent in
// flight), then bucket stores. Mn % 4 == 0 -> no per-row bound check needed.
__device__ __forceinline__ void build_t(const int* __restrict__ idx, int t,
                                        int blk) {
    int base = (blk * 256 + threadIdx.x) * ROWS_PER_THR;
    if (base >= Mn) return;
    const int4* q = (const int4*)idx + (size_t)base * 3 / 4;   // 3 int4 per 4 rows
    int4 q0 = __ldcs(&q[0]), q1 = __ldcs(&q[1]), q2 = __ldcs(&q[2]);
    int vs[ROWS_PER_THR] = {q0.y, q1.x, q1.w, q2.z};
    int slots[ROWS_PER_THR];
#pragma unroll
    for (int k = 0; k < ROWS_PER_THR; k++)
        slots[k] = atomicAdd(&g_cnt[t * Vn + vs[k]], 1);
#pragma unroll
    for (int k = 0; k < ROWS_PER_THR; k++) {
        if (slots[k] < CAP) {
            g_ridx[t][vs[k] * CAP + slots[k]] = base + k;
        } else {
            int p = atomicAdd(&g_ovf_cnt[t], 1);
            g_ovf[t][p] = base + k;
        }
    }
}

// ---------------------------------------------------------------------------
// Gather one vertex-warp for time t. Degree computed inline from the
// adjacency row (one 128B coalesced load + ballot/popc — no invdeg array).
// Bucket in registers, shfl-distributed; lane halves own alternate rows.
// NOTE: no writes besides `out` — gather-side bookkeeping writes regressed
// 3x in R6/R8; all resets live in k4.
__device__ __forceinline__ void gather_t(const float4* __restrict__ feat,
                                         const int* __restrict__ adj,
                                         float4* __restrict__ out, int t,
                                         int v) {
    int lane = threadIdx.x & 31;
    int half = lane >> 4;
    int j = lane & 15;

    // issue early, independent of the feature stream
    int a_ent = __ldg(&adj[((size_t)v * Tn + t) * Nn + lane]);
    int c = g_cnt[t * Vn + v];
    if (c > CAP) c = CAP;
    int r0 = g_ridx[t][v * CAP + lane];

    int deg = __popc(__ballot_sync(0xffffffffu, a_ent >= 0));
    if (deg < 1) deg = 1;

    float4 acc0 = make_float4(0.f, 0.f, 0.f, 0.f);
    float4 acc1 = make_float4(0.f, 0.f, 0.f, 0.f);

    int base = 0;
    for (; base + 15 < c; base += 16) {                  // 16 rows/warp/iter
        int m0 = __shfl_sync(0xffffffffu, r0, (base + half) & 31);
        int m1 = __shfl_sync(0xffffffffu, r0, (base + half + 2) & 31);
        int m2 = __shfl_sync(0xffffffffu, r0, (base + half + 4) & 31);
        int m3 = __shfl_sync(0xffffffffu, r0, (base + half + 6) & 31);
        int m4 = __shfl_sync(0xffffffffu, r0, (base + half + 8) & 31);
        int m5 = __shfl_sync(0xffffffffu, r0, (base + half + 10) & 31);
        int m6 = __shfl_sync(0xffffffffu, r0, (base + half + 12) & 31);
        int m7 = __shfl_sync(0xffffffffu, r0, (base + half + 14) & 31);
        float4 a0 = __ldcs(&feat[(size_t)m0 * 16 + j]);
        float4 a1 = __ldcs(&feat[(size_t)m1 * 16 + j]);
        float4 a2 = __ldcs(&feat[(size_t)m2 * 16 + j]);
        float4 a3 = __ldcs(&feat[(size_t)m3 * 16 + j]);
        float4 a4 = __ldcs(&feat[(size_t)m4 * 16 + j]);
        float4 a5 = __ldcs(&feat[(size_t)m5 * 16 + j]);
        float4 a6 = __ldcs(&feat[(size_t)m6 * 16 + j]);
        float4 a7 = __ldcs(&feat[(size_t)m7 * 16 + j]);
        acc0.x += a0.x + a1.x + a2.x + a3.x;
        acc0.y += a0.y + a1.y + a2.y + a3.y;
        acc0.z += a0.z + a1.z + a2.z + a3.z;
        acc0.w += a0.w + a1.w + a2.w + a3.w;
        acc1.x += a4.x + a5.x + a6.x + a7.x;
        acc1.y += a4.y + a5.y + a6.y + a7.y;
        acc1.z += a4.z + a5.z + a6.z + a7.z;
        acc1.w += a4.w + a5.w + a6.w + a7.w;
    }
    for (; base + 7 < c; base += 8) {
        int m0 = __shfl_sync(0xffffffffu, r0, (base + half) & 31);
        int m1 = __shfl_sync(0xffffffffu, r0, (base + half + 2) & 31);
        int m2 = __shfl_sync(0xffffffffu, r0, (base + half + 4) & 31);
        int m3 = __shfl_sync(0xffffffffu, r0, (base + half + 6) & 31);
        float4 a0 = __ldcs(&feat[(size_t)m0 * 16 + j]);
        float4 a1 = __ldcs(&feat[(size_t)m1 * 16 + j]);
        float4 a2 = __ldcs(&feat[(size_t)m2 * 16 + j]);
        float4 a3 = __ldcs(&feat[(size_t)m3 * 16 + j]);
        acc0.x += a0.x + a1.x + a2.x + a3.x;
        acc0.y += a0.y + a1.y + a2.y + a3.y;
        acc0.z += a0.z + a1.z + a2.z + a3.z;
        acc0.w += a0.w + a1.w + a2.w + a3.w;
    }
    for (; base < c; base += 2) {                        // warp-uniform remainder
        int e = base + half;
        int m = __shfl_sync(0xffffffffu, r0, e & 31);
        if (e < c) {
            float4 a = __ldcs(&feat[(size_t)m * 16 + j]);
            acc0.x += a.x; acc0.y += a.y; acc0.z += a.z; acc0.w += a.w;
        }
    }

    acc0.x += acc1.x; acc0.y += acc1.y; acc0.z += acc1.z; acc0.w += acc1.w;
    acc0.x += __shfl_xor_sync(0xffffffffu, acc0.x, 16);
    acc0.y += __shfl_xor_sync(0xffffffffu, acc0.y, 16);
    acc0.z += __shfl_xor_sync(0xffffffffu, acc0.z, 16);
    acc0.w += __shfl_xor_sync(0xffffffffu, acc0.w, 16);

    if (half == 0) {
        float s = 1.0f / (float)deg;
        acc0.x *= s; acc0.y *= s; acc0.z *= s; acc0.w *= s;
        out[((size_t)(t * Vn + v)) * 16 + j] = acc0;     // full-coverage plain store
    }
}

// ---------------------------------------------------------------------------
// K1: build(t=0) only — degree phase deleted (computed inline by gathers).
__global__ void k1_build0(const int* __restrict__ idx0) {
    build_t(idx0, 0, blockIdx.x);
}

// ---------------------------------------------------------------------------
// K2: gather(t=0) overlapped with build(t=1); every 8th block builds.
__global__ void k2_gather0_build1(const float4* __restrict__ f0,
                                  const int* __restrict__ idx1,
                                  const int* __restrict__ adj,
                                  float4* __restrict__ out) {
    int g = blockIdx.x >> 3, l = blockIdx.x & 7;
    if (l == 7 && g < BUILD_BLOCKS) {
        build_t(idx1, 1, g);
    } else {
        int nb = g < BUILD_BLOCKS ? g : BUILD_BLOCKS;    // build blocks before us
        int gid = blockIdx.x - nb;
        int v = gid * 8 + ((int)threadIdx.x >> 5);
        if (v < Vn) gather_t(f0, adj, out, 0, v);
    }
}

// K3: gather(t=1).
__global__ void k3_gather1(const float4* __restrict__ f1,
                           const int* __restrict__ adj,
                           float4* __restrict__ out) {
    int v = blockIdx.x * 8 + ((int)threadIdx.x >> 5);
    if (v < Vn) gather_t(f1, adj, out, 1, v);
}

// ---------------------------------------------------------------------------
// K4: block 0 alone consumes the tiny overflow lists (degree recomputed from
// adjacency for those rows) and resets g_ovf_cnt; all blocks share the
// vectorized g_cnt reset. Cross-kernel ordering via launch boundaries.
__global__ void k4_fixup(const int* __restrict__ idx0,
                         const int* __restrict__ idx1,
                         const float4* __restrict__ f0,
                         const float4* __restrict__ f1,
                         const int* __restrict__ adj,
                         float* __restrict__ out) {
    int tid = blockIdx.x * blockDim.x + threadIdx.x;
    int nthreads = gridDim.x * blockDim.x;

    if (blockIdx.x == 0) {
#pragma unroll
        for (int t = 0; t < Tn; t++) {
            int n = g_ovf_cnt[t];
            int total = n * (Fn / 4);
            const int* idx = t ? idx1 : idx0;
            const float4* feat = t ? f1 : f0;
            for (int w = threadIdx.x; w < total; w += blockDim.x) {
                int e = w >> 4, j = w & 15;
                int m = g_ovf[t][e];
                int v = idx[m * 3 + 1];
                int deg = 0;
#pragma unroll
                for (int k = 0; k < Nn; k++)
                    deg += (adj[((size_t)v * Tn + t) * Nn + k] >= 0);
                if (deg < 1) deg = 1;
                float s = 1.0f / (float)deg;
                float4 f = feat[(size_t)m * 16 + j];
                float* dst = out + ((size_t)(t * Vn + v) * 16 + j) * 4;
                asm volatile("red.global.add.v4.f32 [%0], {%1, %2, %3, %4};"
                             :: "l"(dst),
                                "f"(f.x * s), "f"(f.y * s), "f"(f.z * s), "f"(f.w * s)
                             : "memory");
            }
        }
        __syncthreads();
        if (threadIdx.x < Tn) g_ovf_cnt[threadIdx.x] = 0;
    }
    // vectorized bucket-counter reset (Tn*Vn = 200000 ints = 50000 int4)
    int4 z = make_int4(0, 0, 0, 0);
    for (int i = tid; i < (Tn * Vn) / 4; i += nthreads)
        ((int4*)g_cnt)[i] = z;
}

// ---------------------------------------------------------------------------
extern "C" void kernel_launch(void* const* d_in, const int* in_sizes, int n_in,
                              void* d_out, int out_size) {
    const int*   adj  = (const int*)  d_in[0];   // [1, V, T, N] int32
    const int*   idx0 = (const int*)  d_in[1];   // [M, 3] int32
    const float* f0   = (const float*)d_in[2];   // [M, F] f32
    const int*   idx1 = (const int*)  d_in[3];
    const float* f1   = (const float*)d_in[4];
    float* out = (float*)d_out;                  // out0 ++ out1, each [V, F]

    k1_build0<<<BUILD_BLOCKS, 256>>>(idx0);

    k2_gather0_build1<<<GATHER_BLOCKS + BUILD_BLOCKS, 256>>>(
        (const float4*)f0, idx1, adj, (float4*)out);

    k3_gather1<<<GATHER_BLOCKS, 256>>>((const float4*)f1, adj, (float4*)out);

    k4_fixup<<<FIX_BLOCKS, 256>>>(idx0, idx1, (const float4*)f0,
                                  (const float4*)f1, adj, out);
}

// round 14
// speedup vs baseline: 1.0193x; 1.0193x over previous
#include <cuda_runtime.h>
#include <cstdint>

// Problem constants (fixed by the reference)
#define Vn 100000
#define Tn 2
#define Nn 32
#define Fn 64
#define Mn 1600000
#define CAP 32   // bucket capacity; overflow -> list + fixup kernel (any input)

// Device scratch (zero-initialized at module load; restored every launch)
__device__ float g_invdeg[Tn * Vn];          // 800 KB
__device__ int   g_cnt[Tn * Vn];             // 800 KB  (reset by k4)
__device__ int   g_ridx[Tn][Vn * CAP];       // 25.6 MB
__device__ int   g_ovf_cnt[Tn];              // reset by k4's last block
__device__ int   g_ovf[Tn][Mn];              // 12.8 MB (full-correctness bound)
__device__ int   g_done;                     // k4 arrival counter

#define ROWS_PER_THR 8
#define BUILD_BLOCKS ((Mn + 256 * ROWS_PER_THR - 1) / (256 * ROWS_PER_THR))  // 782
#define DEG_BLOCKS   ((Vn * Tn * (Nn / 4) + 255) / 256)                      // 6250
#define GATHER_BLOCKS (Vn / 8)                                               // 12500
#define FIX_BLOCKS   128

// ---------------------------------------------------------------------------
// Build one t: 8 rows/thread. Coalesced 6x int4 index loads; all 8 atomics
// issued back-to-back (independent, in flight together), then bucket stores.
// Mn % 8 == 0 -> no per-row bound check needed.
__device__ __forceinline__ void build_t(const int* __restrict__ idx, int t,
                                        int blk) {
    int base = (blk * 256 + threadIdx.x) * ROWS_PER_THR;
    if (base >= Mn) return;
    const int4* q = (const int4*)idx + (size_t)base * 3 / 4;   // 3 int4 per 4 rows
    int4 q0 = __ldcs(&q[0]), q1 = __ldcs(&q[1]), q2 = __ldcs(&q[2]);
    int4 q3 = __ldcs(&q[3]), q4 = __ldcs(&q[4]), q5 = __ldcs(&q[5]);
    int vs[ROWS_PER_THR] = {q0.y, q1.x, q1.w, q2.z, q3.y, q4.x, q4.w, q5.z};
    int slots[ROWS_PER_THR];
#pragma unroll
    for (int k = 0; k < ROWS_PER_THR; k++)
        slots[k] = atomicAdd(&g_cnt[t * Vn + vs[k]], 1);
#pragma unroll
    for (int k = 0; k < ROWS_PER_THR; k++) {
        if (slots[k] < CAP) {
            g_ridx[t][vs[k] * CAP + slots[k]] = base + k;
        } else {
            int p = atomicAdd(&g_ovf_cnt[t], 1);
            g_ovf[t][p] = base + k;
        }
    }
}

// ---------------------------------------------------------------------------
// Gather one vertex-warp for time t. Bucket in registers, shfl-distributed;
// lane halves own alternate rows; up to 8 LDG.128 in flight per warp.
// NOTE: no writes besides `out` — gather-side bookkeeping writes regressed
// 3x in R6/R8; all resets live in k4.
__device__ __forceinline__ void gather_t(const float4* __restrict__ feat,
                                         float4* __restrict__ out, int t,
                                         int v) {
    int lane = threadIdx.x & 31;
    int half = lane >> 4;
    int j = lane & 15;

    int c = g_cnt[t * Vn + v];
    if (c > CAP) c = CAP;
    int r0 = g_ridx[t][v * CAP + lane];

    float4 acc0 = make_float4(0.f, 0.f, 0.f, 0.f);
    float4 acc1 = make_float4(0.f, 0.f, 0.f, 0.f);

    int base = 0;
    for (; base + 15 < c; base += 16) {                  // 16 rows/warp/iter
        int m0 = __shfl_sync(0xffffffffu, r0, (base + half) & 31);
        int m1 = __shfl_sync(0xffffffffu, r0, (base + half + 2) & 31);
        int m2 = __shfl_sync(0xffffffffu, r0, (base + half + 4) & 31);
        int m3 = __shfl_sync(0xffffffffu, r0, (base + half + 6) & 31);
        int m4 = __shfl_sync(0xffffffffu, r0, (base + half + 8) & 31);
        int m5 = __shfl_sync(0xffffffffu, r0, (base + half + 10) & 31);
        int m6 = __shfl_sync(0xffffffffu, r0, (base + half + 12) & 31);
        int m7 = __shfl_sync(0xffffffffu, r0, (base + half + 14) & 31);
        float4 a0 = __ldcs(&feat[(size_t)m0 * 16 + j]);
        float4 a1 = __ldcs(&feat[(size_t)m1 * 16 + j]);
        float4 a2 = __ldcs(&feat[(size_t)m2 * 16 + j]);
        float4 a3 = __ldcs(&feat[(size_t)m3 * 16 + j]);
        float4 a4 = __ldcs(&feat[(size_t)m4 * 16 + j]);
        float4 a5 = __ldcs(&feat[(size_t)m5 * 16 + j]);
        float4 a6 = __ldcs(&feat[(size_t)m6 * 16 + j]);
        float4 a7 = __ldcs(&feat[(size_t)m7 * 16 + j]);
        acc0.x += a0.x + a1.x + a2.x + a3.x;
        acc0.y += a0.y + a1.y + a2.y + a3.y;
        acc0.z += a0.z + a1.z + a2.z + a3.z;
        acc0.w += a0.w + a1.w + a2.w + a3.w;
        acc1.x += a4.x + a5.x + a6.x + a7.x;
        acc1.y += a4.y + a5.y + a6.y + a7.y;
        acc1.z += a4.z + a5.z + a6.z + a7.z;
        acc1.w += a4.w + a5.w + a6.w + a7.w;
    }
    for (; base + 7 < c; base += 8) {
        int m0 = __shfl_sync(0xffffffffu, r0, (base + half) & 31);
        int m1 = __shfl_sync(0xffffffffu, r0, (base + half + 2) & 31);
        int m2 = __shfl_sync(0xffffffffu, r0, (base + half + 4) & 31);
        int m3 = __shfl_sync(0xffffffffu, r0, (base + half + 6) & 31);
        float4 a0 = __ldcs(&feat[(size_t)m0 * 16 + j]);
        float4 a1 = __ldcs(&feat[(size_t)m1 * 16 + j]);
        float4 a2 = __ldcs(&feat[(size_t)m2 * 16 + j]);
        float4 a3 = __ldcs(&feat[(size_t)m3 * 16 + j]);
        acc0.x += a0.x + a1.x + a2.x + a3.x;
        acc0.y += a0.y + a1.y + a2.y + a3.y;
        acc0.z += a0.z + a1.z + a2.z + a3.z;
        acc0.w += a0.w + a1.w + a2.w + a3.w;
    }
    for (; base < c; base += 2) {                        // warp-uniform remainder
        int e = base + half;
        int m = __shfl_sync(0xffffffffu, r0, e & 31);
        if (e < c) {
            float4 a = __ldcs(&feat[(size_t)m * 16 + j]);
            acc0.x += a.x; acc0.y += a.y; acc0.z += a.z; acc0.w += a.w;
        }
    }

    acc0.x += acc1.x; acc0.y += acc1.y; acc0.z += acc1.z; acc0.w += acc1.w;
    acc0.x += __shfl_xor_sync(0xffffffffu, acc0.x, 16);
    acc0.y += __shfl_xor_sync(0xffffffffu, acc0.y, 16);
    acc0.z += __shfl_xor_sync(0xffffffffu, acc0.z, 16);
    acc0.w += __shfl_xor_sync(0xffffffffu, acc0.w, 16);

    if (half == 0) {
        float s = __ldg(&g_invdeg[t * Vn + v]);
        acc0.x *= s; acc0.y *= s; acc0.z *= s; acc0.w *= s;
        out[((size_t)(t * Vn + v)) * 16 + j] = acc0;     // full-coverage plain store
    }
}

// ---------------------------------------------------------------------------
// K1: build(t=0) blocks [0, BUILD_BLOCKS), degree blocks after.
__global__ void k1_build0_degree(const int* __restrict__ idx0,
                                 const int4* __restrict__ adj) {
    if (blockIdx.x < BUILD_BLOCKS) {
        build_t(idx0, 0, blockIdx.x);
    } else {
        int i = (blockIdx.x - BUILD_BLOCKS) * blockDim.x + threadIdx.x;
        if (i >= Vn * Tn * (Nn / 4)) return;
        int4 a = adj[i];
        int cnt = (a.x >= 0) + (a.y >= 0) + (a.z >= 0) + (a.w >= 0);
#pragma unroll
        for (int off = 4; off >= 1; off >>= 1)
            cnt += __shfl_down_sync(0xffffffffu, cnt, off, 8);
        if ((threadIdx.x & 7) == 0) {
            int gi = i >> 3;                              // = v*Tn + t
            int v = gi >> 1, t = gi & 1;
            if (cnt < 1) cnt = 1;
            g_invdeg[t * Vn + v] = 1.0f / (float)cnt;
        }
    }
}

// ---------------------------------------------------------------------------
// K2: gather(t=0) overlapped with build(t=1); every 8th block builds
// (build blocks now 1/16 of the launch — 782 of 13282).
__global__ void k2_gather0_build1(const float4* __restrict__ f0,
                                  const int* __restrict__ idx1,
                                  float4* __restrict__ out) {
    int g = blockIdx.x >> 3, l = blockIdx.x & 7;
    if (l == 7 && g < BUILD_BLOCKS) {
        build_t(idx1, 1, g);
    } else {
        int nb = g < BUILD_BLOCKS ? g : BUILD_BLOCKS;    // build blocks before us
        int gid = blockIdx.x - nb;
        int v = gid * 8 + ((int)threadIdx.x >> 5);
        if (v < Vn) gather_t(f0, out, 0, v);
    }
}

// K3: gather(t=1).
__global__ void k3_gather1(const float4* __restrict__ f1,
                           float4* __restrict__ out) {
    int v = blockIdx.x * 8 + ((int)threadIdx.x >> 5);
    if (v < Vn) gather_t(f1, out, 1, v);
}

// ---------------------------------------------------------------------------
// K4: RED overflow rows (tiny) on top of gather stores, then vectorized
// g_cnt reset; last block zeroes the overflow counters.
__global__ void k4_fixup(const int* __restrict__ idx0,
                         const int* __restrict__ idx1,
                         const float4* __restrict__ f0,
                         const float4* __restrict__ f1,
                         float* __restrict__ out) {
    int tid = blockIdx.x * blockDim.x + threadIdx.x;
    int nthreads = gridDim.x * blockDim.x;
#pragma unroll
    for (int t = 0; t < Tn; t++) {
        int n = g_ovf_cnt[t];
        int total = n * (Fn / 4);
        const int* idx = t ? idx1 : idx0;
        const float4* feat = t ? f1 : f0;
        for (int w = tid; w < total; w += nthreads) {
            int e = w >> 4, j = w & 15;
            int m = g_ovf[t][e];
            int v = idx[m * 3 + 1];
            float s = g_invdeg[t * Vn + v];
            float4 f = feat[(size_t)m * 16 + j];
            float* dst = out + ((size_t)(t * Vn + v) * 16 + j) * 4;
            asm volatile("red.global.add.v4.f32 [%0], {%1, %2, %3, %4};"
                         :: "l"(dst),
                            "f"(f.x * s), "f"(f.y * s), "f"(f.z * s), "f"(f.w * s)
                         : "memory");
        }
    }
    // vectorized bucket-counter reset (Tn*Vn = 200000 ints = 50000 int4)
    int4 z = make_int4(0, 0, 0, 0);
    for (int i = tid; i < (Tn * Vn) / 4; i += nthreads)
        ((int4*)g_cnt)[i] = z;

    __syncthreads();
    __threadfence();
    if (threadIdx.x == 0) {                              // last block zeroes ovf
        int old = atomicAdd(&g_done, 1);
        if (old == (int)gridDim.x - 1) {
            g_ovf_cnt[0] = 0;
            g_ovf_cnt[1] = 0;
            g_done = 0;
        }
    }
}

// ---------------------------------------------------------------------------
extern "C" void kernel_launch(void* const* d_in, const int* in_sizes, int n_in,
                              void* d_out, int out_size) {
    const int*   adj  = (const int*)  d_in[0];   // [1, V, T, N] int32
    const int*   idx0 = (const int*)  d_in[1];   // [M, 3] int32
    const float* f0   = (const float*)d_in[2];   // [M, F] f32
    const int*   idx1 = (const int*)  d_in[3];
    const float* f1   = (const float*)d_in[4];
    float* out = (float*)d_out;                  // out0 ++ out1, each [V, F]

    k1_build0_degree<<<BUILD_BLOCKS + DEG_BLOCKS, 256>>>(idx0, (const int4*)adj);

    k2_gather0_build1<<<GATHER_BLOCKS + BUILD_BLOCKS, 256>>>(
        (const float4*)f0, idx1, (float4*)out);

    k3_gather1<<<GATHER_BLOCKS, 256>>>((const float4*)f1, (float4*)out);

    k4_fixup<<<FIX_BLOCKS, 256>>>(idx0, idx1, (const float4*)f0,
                                  (const float4*)f1, out);
}

// round 15
// speedup vs baseline: 1.0444x; 1.0246x over previous
#include <cuda_runtime.h>
#include <cstdint>

// Problem constants (fixed by the reference)
#define Vn 100000
#define Tn 2
#define Nn 32
#define Fn 64
#define Mn 1600000
#define CAP 32   // bucket capacity; overflow -> list + fixup kernel (any input)

// Device scratch (zero-initialized at module load; restored every launch)
__device__ float g_invdeg[Tn * Vn];          // 800 KB
__device__ int   g_cnt[Tn * Vn];             // 800 KB  (reset by k4)
__device__ int   g_ridx[Tn][Vn * CAP];       // 25.6 MB
__device__ int   g_ovf_cnt[Tn];              // reset by k4's last block
__device__ int   g_ovf[Tn][Mn];              // 12.8 MB (full-correctness bound)
__device__ int   g_done;                     // k4 arrival counter

#define ROWS_PER_THR 4
#define BUILD_BLOCKS ((Mn + 256 * ROWS_PER_THR - 1) / (256 * ROWS_PER_THR))  // 1563
#define DEG_BLOCKS   ((Vn * Tn * (Nn / 4) + 255) / 256)                      // 6250
#define GATHER_BLOCKS (Vn / 8)                                               // 12500
#define FIX_BLOCKS   128

// ---------------------------------------------------------------------------
// Build one t: 4 rows/thread. Atomics batched first (4 independent in
// flight), then bucket stores. Mn % 4 == 0 -> no per-row bound check needed.
__device__ __forceinline__ void build_t(const int* __restrict__ idx, int t,
                                        int blk) {
    int base = (blk * 256 + threadIdx.x) * ROWS_PER_THR;
    if (base >= Mn) return;
    const int4* q = (const int4*)idx + (size_t)base * 3 / 4;   // 3 int4 per 4 rows
    int4 q0 = __ldcs(&q[0]), q1 = __ldcs(&q[1]), q2 = __ldcs(&q[2]);
    int vs[ROWS_PER_THR] = {q0.y, q1.x, q1.w, q2.z};
    int slots[ROWS_PER_THR];
#pragma unroll
    for (int k = 0; k < ROWS_PER_THR; k++)
        slots[k] = atomicAdd(&g_cnt[t * Vn + vs[k]], 1);
#pragma unroll
    for (int k = 0; k < ROWS_PER_THR; k++) {
        if (slots[k] < CAP) {
            g_ridx[t][vs[k] * CAP + slots[k]] = base + k;
        } else {
            int p = atomicAdd(&g_ovf_cnt[t], 1);
            g_ovf[t][p] = base + k;
        }
    }
}

// ---------------------------------------------------------------------------
// Gather one vertex-warp for time t. Bucket in registers, shfl-distributed;
// lane halves own alternate rows; up to 8 LDG.128 in flight per warp.
// Output written with .cs (streaming) — out is write-once/never-re-read, so
// keeping it out of L2 preserves residency for ridx/cnt metadata.
// NOTE: no writes besides `out` — gather-side bookkeeping writes regressed
// 3x in R6/R8; all resets live in k4.
__device__ __forceinline__ void gather_t(const float4* __restrict__ feat,
                                         float4* __restrict__ out, int t,
                                         int v) {
    int lane = threadIdx.x & 31;
    int half = lane >> 4;
    int j = lane & 15;

    int c = g_cnt[t * Vn + v];
    if (c > CAP) c = CAP;
    int r0 = g_ridx[t][v * CAP + lane];

    float4 acc0 = make_float4(0.f, 0.f, 0.f, 0.f);
    float4 acc1 = make_float4(0.f, 0.f, 0.f, 0.f);

    int base = 0;
    for (; base + 15 < c; base += 16) {                  // 16 rows/warp/iter
        int m0 = __shfl_sync(0xffffffffu, r0, (base + half) & 31);
        int m1 = __shfl_sync(0xffffffffu, r0, (base + half + 2) & 31);
        int m2 = __shfl_sync(0xffffffffu, r0, (base + half + 4) & 31);
        int m3 = __shfl_sync(0xffffffffu, r0, (base + half + 6) & 31);
        int m4 = __shfl_sync(0xffffffffu, r0, (base + half + 8) & 31);
        int m5 = __shfl_sync(0xffffffffu, r0, (base + half + 10) & 31);
        int m6 = __shfl_sync(0xffffffffu, r0, (base + half + 12) & 31);
        int m7 = __shfl_sync(0xffffffffu, r0, (base + half + 14) & 31);
        float4 a0 = __ldcs(&feat[(size_t)m0 * 16 + j]);
        float4 a1 = __ldcs(&feat[(size_t)m1 * 16 + j]);
        float4 a2 = __ldcs(&feat[(size_t)m2 * 16 + j]);
        float4 a3 = __ldcs(&feat[(size_t)m3 * 16 + j]);
        float4 a4 = __ldcs(&feat[(size_t)m4 * 16 + j]);
        float4 a5 = __ldcs(&feat[(size_t)m5 * 16 + j]);
        float4 a6 = __ldcs(&feat[(size_t)m6 * 16 + j]);
        float4 a7 = __ldcs(&feat[(size_t)m7 * 16 + j]);
        acc0.x += a0.x + a1.x + a2.x + a3.x;
        acc0.y += a0.y + a1.y + a2.y + a3.y;
        acc0.z += a0.z + a1.z + a2.z + a3.z;
        acc0.w += a0.w + a1.w + a2.w + a3.w;
        acc1.x += a4.x + a5.x + a6.x + a7.x;
        acc1.y += a4.y + a5.y + a6.y + a7.y;
        acc1.z += a4.z + a5.z + a6.z + a7.z;
        acc1.w += a4.w + a5.w + a6.w + a7.w;
    }
    for (; base + 7 < c; base += 8) {
        int m0 = __shfl_sync(0xffffffffu, r0, (base + half) & 31);
        int m1 = __shfl_sync(0xffffffffu, r0, (base + half + 2) & 31);
        int m2 = __shfl_sync(0xffffffffu, r0, (base + half + 4) & 31);
        int m3 = __shfl_sync(0xffffffffu, r0, (base + half + 6) & 31);
        float4 a0 = __ldcs(&feat[(size_t)m0 * 16 + j]);
        float4 a1 = __ldcs(&feat[(size_t)m1 * 16 + j]);
        float4 a2 = __ldcs(&feat[(size_t)m2 * 16 + j]);
        float4 a3 = __ldcs(&feat[(size_t)m3 * 16 + j]);
        acc0.x += a0.x + a1.x + a2.x + a3.x;
        acc0.y += a0.y + a1.y + a2.y + a3.y;
        acc0.z += a0.z + a1.z + a2.z + a3.z;
        acc0.w += a0.w + a1.w + a2.w + a3.w;
    }
    for (; base < c; base += 2) {                        // warp-uniform remainder
        int e = base + half;
        int m = __shfl_sync(0xffffffffu, r0, e & 31);
        if (e < c) {
            float4 a = __ldcs(&feat[(size_t)m * 16 + j]);
            acc0.x += a.x; acc0.y += a.y; acc0.z += a.z; acc0.w += a.w;
        }
    }

    acc0.x += acc1.x; acc0.y += acc1.y; acc0.z += acc1.z; acc0.w += acc1.w;
    acc0.x += __shfl_xor_sync(0xffffffffu, acc0.x, 16);
    acc0.y += __shfl_xor_sync(0xffffffffu, acc0.y, 16);
    acc0.z += __shfl_xor_sync(0xffffffffu, acc0.z, 16);
    acc0.w += __shfl_xor_sync(0xffffffffu, acc0.w, 16);

    if (half == 0) {
        float s = __ldg(&g_invdeg[t * Vn + v]);
        acc0.x *= s; acc0.y *= s; acc0.z *= s; acc0.w *= s;
        __stcs(&out[((size_t)(t * Vn + v)) * 16 + j], acc0);  // streaming store
    }
}

// ---------------------------------------------------------------------------
// K1: build(t=0) blocks [0, BUILD_BLOCKS), degree blocks after.
__global__ void k1_build0_degree(const int* __restrict__ idx0,
                                 const int4* __restrict__ adj) {
    if (blockIdx.x < BUILD_BLOCKS) {
        build_t(idx0, 0, blockIdx.x);
    } else {
        int i = (blockIdx.x - BUILD_BLOCKS) * blockDim.x + threadIdx.x;
        if (i >= Vn * Tn * (Nn / 4)) return;
        int4 a = adj[i];
        int cnt = (a.x >= 0) + (a.y >= 0) + (a.z >= 0) + (a.w >= 0);
#pragma unroll
        for (int off = 4; off >= 1; off >>= 1)
            cnt += __shfl_down_sync(0xffffffffu, cnt, off, 8);
        if ((threadIdx.x & 7) == 0) {
            int gi = i >> 3;                              // = v*Tn + t
            int v = gi >> 1, t = gi & 1;
            if (cnt < 1) cnt = 1;
            g_invdeg[t * Vn + v] = 1.0f / (float)cnt;
        }
    }
}

// ---------------------------------------------------------------------------
// K2: gather(t=0) overlapped with build(t=1); every 8th block builds.
__global__ void k2_gather0_build1(const float4* __restrict__ f0,
                                  const int* __restrict__ idx1,
                                  float4* __restrict__ out) {
    int g = blockIdx.x >> 3, l = blockIdx.x & 7;
    if (l == 7 && g < BUILD_BLOCKS) {
        build_t(idx1, 1, g);
    } else {
        int nb = g < BUILD_BLOCKS ? g : BUILD_BLOCKS;    // build blocks before us
        int gid = blockIdx.x - nb;
        int v = gid * 8 + ((int)threadIdx.x >> 5);
        if (v < Vn) gather_t(f0, out, 0, v);
    }
}

// K3: gather(t=1).
__global__ void k3_gather1(const float4* __restrict__ f1,
                           float4* __restrict__ out) {
    int v = blockIdx.x * 8 + ((int)threadIdx.x >> 5);
    if (v < Vn) gather_t(f1, out, 1, v);
}

// ---------------------------------------------------------------------------
// K4: RED overflow rows (tiny) on top of gather stores, then vectorized
// g_cnt reset; last block zeroes the overflow counters.
__global__ void k4_fixup(const int* __restrict__ idx0,
                         const int* __restrict__ idx1,
                         const float4* __restrict__ f0,
                         const float4* __restrict__ f1,
                         float* __restrict__ out) {
    int tid = blockIdx.x * blockDim.x + threadIdx.x;
    int nthreads = gridDim.x * blockDim.x;
#pragma unroll
    for (int t = 0; t < Tn; t++) {
        int n = g_ovf_cnt[t];
        int total = n * (Fn / 4);
        const int* idx = t ? idx1 : idx0;
        const float4* feat = t ? f1 : f0;
        for (int w = tid; w < total; w += nthreads) {
            int e = w >> 4, j = w & 15;
            int m = g_ovf[t][e];
            int v = idx[m * 3 + 1];
            float s = g_invdeg[t * Vn + v];
            float4 f = feat[(size_t)m * 16 + j];
            float* dst = out + ((size_t)(t * Vn + v) * 16 + j) * 4;
            asm volatile("red.global.add.v4.f32 [%0], {%1, %2, %3, %4};"
                         :: "l"(dst),
                            "f"(f.x * s), "f"(f.y * s), "f"(f.z * s), "f"(f.w * s)
                         : "memory");
        }
    }
    // vectorized bucket-counter reset (Tn*Vn = 200000 ints = 50000 int4)
    int4 z = make_int4(0, 0, 0, 0);
    for (int i = tid; i < (Tn * Vn) / 4; i += nthreads)
        ((int4*)g_cnt)[i] = z;

    __syncthreads();
    __threadfence();
    if (threadIdx.x == 0) {                              // last block zeroes ovf
        int old = atomicAdd(&g_done, 1);
        if (old == (int)gridDim.x - 1) {
            g_ovf_cnt[0] = 0;
            g_ovf_cnt[1] = 0;
            g_done = 0;
        }
    }
}

// ---------------------------------------------------------------------------
extern "C" void kernel_launch(void* const* d_in, const int* in_sizes, int n_in,
                              void* d_out, int out_size) {
    const int*   adj  = (const int*)  d_in[0];   // [1, V, T, N] int32
    const int*   idx0 = (const int*)  d_in[1];   // [M, 3] int32
    const float* f0   = (const float*)d_in[2];   // [M, F] f32
    const int*   idx1 = (const int*)  d_in[3];
    const float* f1   = (const float*)d_in[4];
    float* out = (float*)d_out;                  // out0 ++ out1, each [V, F]

    k1_build0_degree<<<BUILD_BLOCKS + DEG_BLOCKS, 256>>>(idx0, (const int4*)adj);

    k2_gather0_build1<<<GATHER_BLOCKS + BUILD_BLOCKS, 256>>>(
        (const float4*)f0, idx1, (float4*)out);

    k3_gather1<<<GATHER_BLOCKS, 256>>>((const float4*)f1, (float4*)out);

    k4_fixup<<<FIX_BLOCKS, 256>>>(idx0, idx1, (const float4*)f0,
                                  (const float4*)f1, out);
}

// round 16
// speedup vs baseline: 1.0540x; 1.0092x over previous
#include <cuda_runtime.h>
#include <cstdint>

// Problem constants (fixed by the reference)
#define Vn 100000
#define Tn 2
#define Nn 32
#define Fn 64
#define Mn 1600000
#define CAP 32   // bucket capacity; overflow -> list + fixup (any input)

// Device scratch (zero-initialized at module load; restored every launch)
__device__ float g_invdeg[Tn * Vn];          // 800 KB
__device__ int   g_cnt[Tn * Vn];             // 800 KB (t=0 reset in k3 tail, t=1 in k4)
__device__ int   g_ridx[Tn][Vn * CAP];       // 25.6 MB
__device__ int   g_ovf_cnt[Tn];              // [0] reset in k3 tail, [1] in k4
__device__ int   g_ovf[Tn][Mn];              // 12.8 MB (full-correctness bound)
__device__ int   g_done;                     // k4 arrival counter

#define ROWS_PER_THR 4
#define BUILD_BLOCKS ((Mn + 256 * ROWS_PER_THR - 1) / (256 * ROWS_PER_THR))  // 1563
#define DEG_BLOCKS   ((Vn * Tn * (Nn / 4) + 255) / 256)                      // 6250
#define GATHER_BLOCKS (Vn / 8)                                               // 12500
#define TAIL_BLOCKS  64
#define FIX_BLOCKS   128

// ---------------------------------------------------------------------------
// Build one t: 4 rows/thread. Atomics batched first (4 independent in
// flight), then bucket stores. Mn % 4 == 0 -> no per-row bound check needed.
__device__ __forceinline__ void build_t(const int* __restrict__ idx, int t,
                                        int blk) {
    int base = (blk * 256 + threadIdx.x) * ROWS_PER_THR;
    if (base >= Mn) return;
    const int4* q = (const int4*)idx + (size_t)base * 3 / 4;   // 3 int4 per 4 rows
    int4 q0 = __ldcs(&q[0]), q1 = __ldcs(&q[1]), q2 = __ldcs(&q[2]);
    int vs[ROWS_PER_THR] = {q0.y, q1.x, q1.w, q2.z};
    int slots[ROWS_PER_THR];
#pragma unroll
    for (int k = 0; k < ROWS_PER_THR; k++)
        slots[k] = atomicAdd(&g_cnt[t * Vn + vs[k]], 1);
#pragma unroll
    for (int k = 0; k < ROWS_PER_THR; k++) {
        if (slots[k] < CAP) {
            g_ridx[t][vs[k] * CAP + slots[k]] = base + k;
        } else {
            int p = atomicAdd(&g_ovf_cnt[t], 1);
            g_ovf[t][p] = base + k;
        }
    }
}

// ---------------------------------------------------------------------------
// Overflow fixup for one t (tiny: ~tens of rows). REDs scaled rows on top of
// gather stores. Caller guarantees all gathers for this t have completed
// (launch-boundary ordering).
__device__ __forceinline__ void fixup_t(const int* __restrict__ idx,
                                        const float4* __restrict__ feat,
                                        float* __restrict__ out, int t) {
    int n = g_ovf_cnt[t];
    int total = n * (Fn / 4);
    for (int w = threadIdx.x; w < total; w += blockDim.x) {
        int e = w >> 4, j = w & 15;
        int m = g_ovf[t][e];
        int v = idx[m * 3 + 1];
        float s = g_invdeg[t * Vn + v];
        float4 f = feat[(size_t)m * 16 + j];
        float* dst = out + ((size_t)(t * Vn + v) * 16 + j) * 4;
        asm volatile("red.global.add.v4.f32 [%0], {%1, %2, %3, %4};"
                     :: "l"(dst),
                        "f"(f.x * s), "f"(f.y * s), "f"(f.z * s), "f"(f.w * s)
                     : "memory");
    }
    __syncthreads();
    if (threadIdx.x == 0) g_ovf_cnt[t] = 0;   // sole-toucher reset, no fence
}

// ---------------------------------------------------------------------------
// Gather one vertex-warp for time t. Bucket in registers, shfl-distributed;
// lane halves own alternate rows; up to 8 LDG.128 in flight per warp.
// Streaming loads+stores keep L2 for ridx/cnt metadata.
// NOTE: no writes besides `out` — gather-side bookkeeping writes regressed
// 3x in R6/R8; all resets live in the tail blocks / k4.
__device__ __forceinline__ void gather_t(const float4* __restrict__ feat,
                                         float4* __restrict__ out, int t,
                                         int v) {
    int lane = threadIdx.x & 31;
    int half = lane >> 4;
    int j = lane & 15;

    int c = g_cnt[t * Vn + v];
    if (c > CAP) c = CAP;
    int r0 = g_ridx[t][v * CAP + lane];

    float4 acc0 = make_float4(0.f, 0.f, 0.f, 0.f);
    float4 acc1 = make_float4(0.f, 0.f, 0.f, 0.f);

    int base = 0;
    for (; base + 15 < c; base += 16) {                  // 16 rows/warp/iter
        int m0 = __shfl_sync(0xffffffffu, r0, (base + half) & 31);
        int m1 = __shfl_sync(0xffffffffu, r0, (base + half + 2) & 31);
        int m2 = __shfl_sync(0xffffffffu, r0, (base + half + 4) & 31);
        int m3 = __shfl_sync(0xffffffffu, r0, (base + half + 6) & 31);
        int m4 = __shfl_sync(0xffffffffu, r0, (base + half + 8) & 31);
        int m5 = __shfl_sync(0xffffffffu, r0, (base + half + 10) & 31);
        int m6 = __shfl_sync(0xffffffffu, r0, (base + half + 12) & 31);
        int m7 = __shfl_sync(0xffffffffu, r0, (base + half + 14) & 31);
        float4 a0 = __ldcs(&feat[(size_t)m0 * 16 + j]);
        float4 a1 = __ldcs(&feat[(size_t)m1 * 16 + j]);
        float4 a2 = __ldcs(&feat[(size_t)m2 * 16 + j]);
        float4 a3 = __ldcs(&feat[(size_t)m3 * 16 + j]);
        float4 a4 = __ldcs(&feat[(size_t)m4 * 16 + j]);
        float4 a5 = __ldcs(&feat[(size_t)m5 * 16 + j]);
        float4 a6 = __ldcs(&feat[(size_t)m6 * 16 + j]);
        float4 a7 = __ldcs(&feat[(size_t)m7 * 16 + j]);
        acc0.x += a0.x + a1.x + a2.x + a3.x;
        acc0.y += a0.y + a1.y + a2.y + a3.y;
        acc0.z += a0.z + a1.z + a2.z + a3.z;
        acc0.w += a0.w + a1.w + a2.w + a3.w;
        acc1.x += a4.x + a5.x + a6.x + a7.x;
        acc1.y += a4.y + a5.y + a6.y + a7.y;
        acc1.z += a4.z + a5.z + a6.z + a7.z;
        acc1.w += a4.w + a5.w + a6.w + a7.w;
    }
    for (; base + 7 < c; base += 8) {
        int m0 = __shfl_sync(0xffffffffu, r0, (base + half) & 31);
        int m1 = __shfl_sync(0xffffffffu, r0, (base + half + 2) & 31);
        int m2 = __shfl_sync(0xffffffffu, r0, (base + half + 4) & 31);
        int m3 = __shfl_sync(0xffffffffu, r0, (base + half + 6) & 31);
        float4 a0 = __ldcs(&feat[(size_t)m0 * 16 + j]);
        float4 a1 = __ldcs(&feat[(size_t)m1 * 16 + j]);
        float4 a2 = __ldcs(&feat[(size_t)m2 * 16 + j]);
        float4 a3 = __ldcs(&feat[(size_t)m3 * 16 + j]);
        acc0.x += a0.x + a1.x + a2.x + a3.x;
        acc0.y += a0.y + a1.y + a2.y + a3.y;
        acc0.z += a0.z + a1.z + a2.z + a3.z;
        acc0.w += a0.w + a1.w + a2.w + a3.w;
    }
    for (; base < c; base += 2) {                        // warp-uniform remainder
        int e = base + half;
        int m = __shfl_sync(0xffffffffu, r0, e & 31);
        if (e < c) {
            float4 a = __ldcs(&feat[(size_t)m * 16 + j]);
            acc0.x += a.x; acc0.y += a.y; acc0.z += a.z; acc0.w += a.w;
        }
    }

    acc0.x += acc1.x; acc0.y += acc1.y; acc0.z += acc1.z; acc0.w += acc1.w;
    acc0.x += __shfl_xor_sync(0xffffffffu, acc0.x, 16);
    acc0.y += __shfl_xor_sync(0xffffffffu, acc0.y, 16);
    acc0.z += __shfl_xor_sync(0xffffffffu, acc0.z, 16);
    acc0.w += __shfl_xor_sync(0xffffffffu, acc0.w, 16);

    if (half == 0) {
        float s = __ldg(&g_invdeg[t * Vn + v]);
        acc0.x *= s; acc0.y *= s; acc0.z *= s; acc0.w *= s;
        __stcs(&out[((size_t)(t * Vn + v)) * 16 + j], acc0);  // streaming store
    }
}

// ---------------------------------------------------------------------------
// K1: build(t=0) blocks [0, BUILD_BLOCKS), degree blocks after.
__global__ void k1_build0_degree(const int* __restrict__ idx0,
                                 const int4* __restrict__ adj) {
    if (blockIdx.x < BUILD_BLOCKS) {
        build_t(idx0, 0, blockIdx.x);
    } else {
        int i = (blockIdx.x - BUILD_BLOCKS) * blockDim.x + threadIdx.x;
        if (i >= Vn * Tn * (Nn / 4)) return;
        int4 a = adj[i];
        int cnt = (a.x >= 0) + (a.y >= 0) + (a.z >= 0) + (a.w >= 0);
#pragma unroll
        for (int off = 4; off >= 1; off >>= 1)
            cnt += __shfl_down_sync(0xffffffffu, cnt, off, 8);
        if ((threadIdx.x & 7) == 0) {
            int gi = i >> 3;                              // = v*Tn + t
            int v = gi >> 1, t = gi & 1;
            if (cnt < 1) cnt = 1;
            g_invdeg[t * Vn + v] = 1.0f / (float)cnt;
        }
    }
}

// ---------------------------------------------------------------------------
// K2: gather(t=0) overlapped with build(t=1); every 8th block builds.
__global__ void k2_gather0_build1(const float4* __restrict__ f0,
                                  const int* __restrict__ idx1,
                                  float4* __restrict__ out) {
    int g = blockIdx.x >> 3, l = blockIdx.x & 7;
    if (l == 7 && g < BUILD_BLOCKS) {
        build_t(idx1, 1, g);
    } else {
        int nb = g < BUILD_BLOCKS ? g : BUILD_BLOCKS;    // build blocks before us
        int gid = blockIdx.x - nb;
        int v = gid * 8 + ((int)threadIdx.x >> 5);
        if (v < Vn) gather_t(f0, out, 0, v);
    }
}

// ---------------------------------------------------------------------------
// K3: gather(t=1) + TAIL_BLOCKS cheap tail blocks handling all t=0 cleanup.
// Safe: every t=0 producer/consumer (k1 build0/degree, k2 gather0) completed
// at the k2->k3 launch boundary, and k3's gathers touch only t=1 state.
__global__ void k3_gather1_tail0(const float4* __restrict__ f1,
                                 const int* __restrict__ idx0,
                                 const float4* __restrict__ f0,
                                 float4* __restrict__ out) {
    if (blockIdx.x < GATHER_BLOCKS) {
        int v = blockIdx.x * 8 + ((int)threadIdx.x >> 5);
        if (v < Vn) gather_t(f1, out, 1, v);
        return;
    }
    int ebid = blockIdx.x - GATHER_BLOCKS;               // 0 .. TAIL_BLOCKS-1
    if (ebid == 0)                                       // t=0 overflow fixup
        fixup_t(idx0, f0, (float*)out, 0);
    // all tail blocks: reset t=0 bucket counters (Vn ints = Vn/4 int4)
    int4 z = make_int4(0, 0, 0, 0);
    for (int i = ebid * 256 + threadIdx.x; i < Vn / 4; i += TAIL_BLOCKS * 256)
        ((int4*)g_cnt)[i] = z;
}

// ---------------------------------------------------------------------------
// K4: t=1 cleanup only — block 0 does t=1 overflow fixup + g_ovf_cnt[1]
// reset (sole toucher, no fence); all blocks reset t=1 bucket counters.
__global__ void k4_fixup1(const int* __restrict__ idx1,
                          const float4* __restrict__ f1,
                          float* __restrict__ out) {
    if (blockIdx.x == 0)
        fixup_t(idx1, f1, out, 1);
    int4 z = make_int4(0, 0, 0, 0);
    int tid = blockIdx.x * blockDim.x + threadIdx.x;
    int nthreads = gridDim.x * blockDim.x;
    int4* cnt1 = (int4*)(g_cnt + Vn);                    // Vn % 4 == 0, 16B-aligned
    for (int i = tid; i < Vn / 4; i += nthreads)
        cnt1[i] = z;
}

// ---------------------------------------------------------------------------
extern "C" void kernel_launch(void* const* d_in, const int* in_sizes, int n_in,
                              void* d_out, int out_size) {
    const int*   adj  = (const int*)  d_in[0];   // [1, V, T, N] int32
    const int*   idx0 = (const int*)  d_in[1];   // [M, 3] int32
    const float* f0   = (const float*)d_in[2];   // [M, F] f32
    const int*   idx1 = (const int*)  d_in[3];
    const float* f1   = (const float*)d_in[4];
    float* out = (float*)d_out;                  // out0 ++ out1, each [V, F]

    k1_build0_degree<<<BUILD_BLOCKS + DEG_BLOCKS, 256>>>(idx0, (const int4*)adj);

    k2_gather0_build1<<<GATHER_BLOCKS + BUILD_BLOCKS, 256>>>(
        (const float4*)f0, idx1, (float4*)out);

    k3_gather1_tail0<<<GATHER_BLOCKS + TAIL_BLOCKS, 256>>>(
        (const float4*)f1, idx0, (const float4*)f0, (float4*)out);

    k4_fixup1<<<FIX_BLOCKS, 256>>>(idx1, (const float4*)f1, out);
}

// round 17
// speedup vs baseline: 1.0561x; 1.0020x over previous
#include <cuda_runtime.h>
#include <cstdint>

// Problem constants (fixed by the reference)
#define Vn 100000
#define Tn 2
#define Nn 32
#define Fn 64
#define Mn 1600000
#define CAP 32   // bucket capacity; overflow -> list + fixup (any input)

// Device scratch (zero-initialized at module load; restored every launch:
// cnt0 reset in k3 tail, cnt1 reset in NEXT call's k1 tail, ovf counters in
// the respective fixups)
__device__ float g_invdeg[Tn * Vn];          // 800 KB
__device__ int   g_cnt[Tn * Vn];             // 800 KB
__device__ int   g_ridx[Tn][Vn * CAP];       // 25.6 MB
__device__ int   g_ovf_cnt[Tn];
__device__ int   g_ovf[Tn][Mn];              // 12.8 MB (full-correctness bound)

#define ROWS_PER_THR 4
#define BUILD_BLOCKS ((Mn + 256 * ROWS_PER_THR - 1) / (256 * ROWS_PER_THR))  // 1563
#define DEG_BLOCKS   ((Vn * Tn * (Nn / 4) + 255) / 256)                      // 6250
#define GATHER_BLOCKS (Vn / 8)                                               // 12500
#define TAIL_BLOCKS  64

// ---------------------------------------------------------------------------
// Build one t: 4 rows/thread. Atomics batched first (4 independent in
// flight), then bucket stores. Mn % 4 == 0 -> no per-row bound check needed.
__device__ __forceinline__ void build_t(const int* __restrict__ idx, int t,
                                        int blk) {
    int base = (blk * 256 + threadIdx.x) * ROWS_PER_THR;
    if (base >= Mn) return;
    const int4* q = (const int4*)idx + (size_t)base * 3 / 4;   // 3 int4 per 4 rows
    int4 q0 = __ldcs(&q[0]), q1 = __ldcs(&q[1]), q2 = __ldcs(&q[2]);
    int vs[ROWS_PER_THR] = {q0.y, q1.x, q1.w, q2.z};
    int slots[ROWS_PER_THR];
#pragma unroll
    for (int k = 0; k < ROWS_PER_THR; k++)
        slots[k] = atomicAdd(&g_cnt[t * Vn + vs[k]], 1);
#pragma unroll
    for (int k = 0; k < ROWS_PER_THR; k++) {
        if (slots[k] < CAP) {
            g_ridx[t][vs[k] * CAP + slots[k]] = base + k;
        } else {
            int p = atomicAdd(&g_ovf_cnt[t], 1);
            g_ovf[t][p] = base + k;
        }
    }
}

// ---------------------------------------------------------------------------
// Overflow fixup for one t (tiny: ~tens of rows). REDs scaled rows on top of
// gather stores; resets g_ovf_cnt[t] (sole toucher, launch-boundary ordered).
__device__ __forceinline__ void fixup_t(const int* __restrict__ idx,
                                        const float4* __restrict__ feat,
                                        float* __restrict__ out, int t) {
    int n = g_ovf_cnt[t];
    int total = n * (Fn / 4);
    for (int w = threadIdx.x; w < total; w += blockDim.x) {
        int e = w >> 4, j = w & 15;
        int m = g_ovf[t][e];
        int v = idx[m * 3 + 1];
        float s = g_invdeg[t * Vn + v];
        float4 f = feat[(size_t)m * 16 + j];
        float* dst = out + ((size_t)(t * Vn + v) * 16 + j) * 4;
        asm volatile("red.global.add.v4.f32 [%0], {%1, %2, %3, %4};"
                     :: "l"(dst),
                        "f"(f.x * s), "f"(f.y * s), "f"(f.z * s), "f"(f.w * s)
                     : "memory");
    }
    __syncthreads();
    if (threadIdx.x == 0) g_ovf_cnt[t] = 0;
}

// ---------------------------------------------------------------------------
// Gather one vertex-warp for time t. Bucket in registers, shfl-distributed;
// lane halves own alternate rows; up to 8 LDG.128 in flight per warp.
// Streaming loads+stores keep L2 for ridx/cnt metadata.
// NOTE: no writes besides `out` — gather-side bookkeeping writes regressed
// 3x in R6/R8; all resets live in the tail blocks / fixups.
__device__ __forceinline__ void gather_t(const float4* __restrict__ feat,
                                         float4* __restrict__ out, int t,
                                         int v) {
    int lane = threadIdx.x & 31;
    int half = lane >> 4;
    int j = lane & 15;

    int c = g_cnt[t * Vn + v];
    if (c > CAP) c = CAP;
    int r0 = g_ridx[t][v * CAP + lane];

    float4 acc0 = make_float4(0.f, 0.f, 0.f, 0.f);
    float4 acc1 = make_float4(0.f, 0.f, 0.f, 0.f);

    int base = 0;
    for (; base + 15 < c; base += 16) {                  // 16 rows/warp/iter
        int m0 = __shfl_sync(0xffffffffu, r0, (base + half) & 31);
        int m1 = __shfl_sync(0xffffffffu, r0, (base + half + 2) & 31);
        int m2 = __shfl_sync(0xffffffffu, r0, (base + half + 4) & 31);
        int m3 = __shfl_sync(0xffffffffu, r0, (base + half + 6) & 31);
        int m4 = __shfl_sync(0xffffffffu, r0, (base + half + 8) & 31);
        int m5 = __shfl_sync(0xffffffffu, r0, (base + half + 10) & 31);
        int m6 = __shfl_sync(0xffffffffu, r0, (base + half + 12) & 31);
        int m7 = __shfl_sync(0xffffffffu, r0, (base + half + 14) & 31);
        float4 a0 = __ldcs(&feat[(size_t)m0 * 16 + j]);
        float4 a1 = __ldcs(&feat[(size_t)m1 * 16 + j]);
        float4 a2 = __ldcs(&feat[(size_t)m2 * 16 + j]);
        float4 a3 = __ldcs(&feat[(size_t)m3 * 16 + j]);
        float4 a4 = __ldcs(&feat[(size_t)m4 * 16 + j]);
        float4 a5 = __ldcs(&feat[(size_t)m5 * 16 + j]);
        float4 a6 = __ldcs(&feat[(size_t)m6 * 16 + j]);
        float4 a7 = __ldcs(&feat[(size_t)m7 * 16 + j]);
        acc0.x += a0.x + a1.x + a2.x + a3.x;
        acc0.y += a0.y + a1.y + a2.y + a3.y;
        acc0.z += a0.z + a1.z + a2.z + a3.z;
        acc0.w += a0.w + a1.w + a2.w + a3.w;
        acc1.x += a4.x + a5.x + a6.x + a7.x;
        acc1.y += a4.y + a5.y + a6.y + a7.y;
        acc1.z += a4.z + a5.z + a6.z + a7.z;
        acc1.w += a4.w + a5.w + a6.w + a7.w;
    }
    for (; base + 7 < c; base += 8) {
        int m0 = __shfl_sync(0xffffffffu, r0, (base + half) & 31);
        int m1 = __shfl_sync(0xffffffffu, r0, (base + half + 2) & 31);
        int m2 = __shfl_sync(0xffffffffu, r0, (base + half + 4) & 31);
        int m3 = __shfl_sync(0xffffffffu, r0, (base + half + 6) & 31);
        float4 a0 = __ldcs(&feat[(size_t)m0 * 16 + j]);
        float4 a1 = __ldcs(&feat[(size_t)m1 * 16 + j]);
        float4 a2 = __ldcs(&feat[(size_t)m2 * 16 + j]);
        float4 a3 = __ldcs(&feat[(size_t)m3 * 16 + j]);
        acc0.x += a0.x + a1.x + a2.x + a3.x;
        acc0.y += a0.y + a1.y + a2.y + a3.y;
        acc0.z += a0.z + a1.z + a2.z + a3.z;
        acc0.w += a0.w + a1.w + a2.w + a3.w;
    }
    for (; base < c; base += 2) {                        // warp-uniform remainder
        int e = base + half;
        int m = __shfl_sync(0xffffffffu, r0, e & 31);
        if (e < c) {
            float4 a = __ldcs(&feat[(size_t)m * 16 + j]);
            acc0.x += a.x; acc0.y += a.y; acc0.z += a.z; acc0.w += a.w;
        }
    }

    acc0.x += acc1.x; acc0.y += acc1.y; acc0.z += acc1.z; acc0.w += acc1.w;
    acc0.x += __shfl_xor_sync(0xffffffffu, acc0.x, 16);
    acc0.y += __shfl_xor_sync(0xffffffffu, acc0.y, 16);
    acc0.z += __shfl_xor_sync(0xffffffffu, acc0.z, 16);
    acc0.w += __shfl_xor_sync(0xffffffffu, acc0.w, 16);

    if (half == 0) {
        float s = __ldg(&g_invdeg[t * Vn + v]);
        acc0.x *= s; acc0.y *= s; acc0.z *= s; acc0.w *= s;
        __stcs(&out[((size_t)(t * Vn + v)) * 16 + j], acc0);  // streaming store
    }
}

// ---------------------------------------------------------------------------
// K1: build(t=0) blocks, then degree blocks, then TAIL_BLOCKS that reset the
// t=1 bucket counters for THIS call's build1 (previous call's k3 already
// consumed them; launch boundaries order both sides). cnt1 is disjoint from
// everything else k1 touches. First call sees module-load zeros.
__global__ void k1_build0_degree(const int* __restrict__ idx0,
                                 const int4* __restrict__ adj) {
    if (blockIdx.x < BUILD_BLOCKS) {
        build_t(idx0, 0, blockIdx.x);
    } else if (blockIdx.x < BUILD_BLOCKS + DEG_BLOCKS) {
        int i = (blockIdx.x - BUILD_BLOCKS) * blockDim.x + threadIdx.x;
        if (i >= Vn * Tn * (Nn / 4)) return;
        int4 a = adj[i];
        int cnt = (a.x >= 0) + (a.y >= 0) + (a.z >= 0) + (a.w >= 0);
#pragma unroll
        for (int off = 4; off >= 1; off >>= 1)
            cnt += __shfl_down_sync(0xffffffffu, cnt, off, 8);
        if ((threadIdx.x & 7) == 0) {
            int gi = i >> 3;                              // = v*Tn + t
            int v = gi >> 1, t = gi & 1;
            if (cnt < 1) cnt = 1;
            g_invdeg[t * Vn + v] = 1.0f / (float)cnt;
        }
    } else {
        // reset cnt1 (Vn ints = Vn/4 int4); Vn % 4 == 0, 16B-aligned
        int ebid = blockIdx.x - BUILD_BLOCKS - DEG_BLOCKS;
        int4 z = make_int4(0, 0, 0, 0);
        int4* cnt1 = (int4*)(g_cnt + Vn);
        for (int i = ebid * 256 + threadIdx.x; i < Vn / 4;
             i += TAIL_BLOCKS * 256)
            cnt1[i] = z;
    }
}

// ---------------------------------------------------------------------------
// K2: gather(t=0) overlapped with build(t=1); every 8th block builds.
__global__ void k2_gather0_build1(const float4* __restrict__ f0,
                                  const int* __restrict__ idx1,
                                  float4* __restrict__ out) {
    int g = blockIdx.x >> 3, l = blockIdx.x & 7;
    if (l == 7 && g < BUILD_BLOCKS) {
        build_t(idx1, 1, g);
    } else {
        int nb = g < BUILD_BLOCKS ? g : BUILD_BLOCKS;    // build blocks before us
        int gid = blockIdx.x - nb;
        int v = gid * 8 + ((int)threadIdx.x >> 5);
        if (v < Vn) gather_t(f0, out, 0, v);
    }
}

// ---------------------------------------------------------------------------
// K3: gather(t=1) + TAIL_BLOCKS tail blocks handling all t=0 cleanup.
// Safe: every t=0 producer/consumer completed at the k2->k3 boundary, and
// k3's gathers touch only t=1 state.
__global__ void k3_gather1_tail0(const float4* __restrict__ f1,
                                 const int* __restrict__ idx0,
                                 const float4* __restrict__ f0,
                                 float4* __restrict__ out) {
    if (blockIdx.x < GATHER_BLOCKS) {
        int v = blockIdx.x * 8 + ((int)threadIdx.x >> 5);
        if (v < Vn) gather_t(f1, out, 1, v);
        return;
    }
    int ebid = blockIdx.x - GATHER_BLOCKS;               // 0 .. TAIL_BLOCKS-1
    if (ebid == 0)                                       // t=0 overflow fixup
        fixup_t(idx0, f0, (float*)out, 0);
    // all tail blocks: reset t=0 bucket counters (Vn ints = Vn/4 int4)
    int4 z = make_int4(0, 0, 0, 0);
    for (int i = ebid * 256 + threadIdx.x; i < Vn / 4; i += TAIL_BLOCKS * 256)
        ((int4*)g_cnt)[i] = z;
}

// ---------------------------------------------------------------------------
// K4: single block — t=1 overflow fixup only (zero iterations normally).
// cnt1 reset migrated to the next call's k1 tail.
__global__ void k4_fixup1(const int* __restrict__ idx1,
                          const float4* __restrict__ f1,
                          float* __restrict__ out) {
    fixup_t(idx1, f1, out, 1);
}

// ---------------------------------------------------------------------------
extern "C" void kernel_launch(void* const* d_in, const int* in_sizes, int n_in,
                              void* d_out, int out_size) {
    const int*   adj  = (const int*)  d_in[0];   // [1, V, T, N] int32
    const int*   idx0 = (const int*)  d_in[1];   // [M, 3] int32
    const float* f0   = (const float*)d_in[2];   // [M, F] f32
    const int*   idx1 = (const int*)  d_in[3];
    const float* f1   = (const float*)d_in[4];
    float* out = (float*)d_out;                  // out0 ++ out1, each [V, F]

    k1_build0_degree<<<BUILD_BLOCKS + DEG_BLOCKS + TAIL_BLOCKS, 256>>>(
        idx0, (const int4*)adj);

    k2_gather0_build1<<<GATHER_BLOCKS + BUILD_BLOCKS, 256>>>(
        (const float4*)f0, idx1, (float4*)out);

    k3_gather1_tail0<<<GATHER_BLOCKS + TAIL_BLOCKS, 256>>>(
        (const float4*)f1, idx0, (const float4*)f0, (float4*)out);

    k4_fixup1<<<1, 256>>>(idx1, (const float4*)f1, out);
}